// round 2
// baseline (speedup 1.0000x reference)
#include <cuda_runtime.h>
#include <cuda_bf16.h>
#include <math.h>

// Problem constants
#define B  64
#define L  2048
#define H  1024
#define V  32000
#define P  128
#define H2 2048          // 2*H
#define KO 1152          // H + P

#define CHUNKS 32        // L-splits for attention
#define LC (L / CHUNKS)  // 64
#define PS (H + 4)       // partial stride (16B aligned)

typedef unsigned long long U64;

union U64F2 { U64 u; float2 f; };

__device__ __forceinline__ U64 fma2(U64 a, U64 b, U64 c) {
    U64 d;
    asm("fma.rn.f32x2 %0, %1, %2, %3;" : "=l"(d) : "l"(a), "l"(b), "l"(c));
    return d;
}
__device__ __forceinline__ U64 mul2(U64 a, U64 b) {
    U64 d;
    asm("mul.rn.f32x2 %0, %1, %2;" : "=l"(d) : "l"(a), "l"(b));
    return d;
}
__device__ __forceinline__ float hsum2(U64 a) {
    U64F2 t; t.u = a; return t.f.x + t.f.y;
}
__device__ __forceinline__ U64 dup2(float x) {
    U64F2 t; t.f.x = x; t.f.y = x; return t.u;
}

// Scratch (device globals — no allocation allowed)
__device__ float g_hnew[B * H];
__device__ float g_cat[B * H2];                 // [h_new | context]
__device__ float g_catp[B * KO];                // [concat_out | prior]
__device__ float g_energy[B * L];
__device__ float g_part[B * CHUNKS * PS];       // ctx partial + (m, s)

// ---------------------------------------------------------------------------
// Kernel 1: GRU cell. Block per output column c. 8 warps x 8 batches each
// (processed in two halves of 4 to limit register pressure).
// ---------------------------------------------------------------------------
__global__ void gru_kernel(const int* __restrict__ seq,
                           const float* __restrict__ lh,
                           const float* __restrict__ emb,
                           const float* __restrict__ Wih,
                           const float* __restrict__ Whh,
                           const float* __restrict__ bih,
                           const float* __restrict__ bhh,
                           float* __restrict__ out_h)
{
    int c    = blockIdx.x;
    int tid  = threadIdx.x;
    int warp = tid >> 5;
    int lane = tid & 31;

    __shared__ int xrow[B];
    if (tid < B) xrow[tid] = seq[tid];   // input_seq is int32 (JAX x64 disabled)
    __syncthreads();

    const float* wr = Wih + (size_t)c * H;
    const float* wz = Wih + (size_t)(c + H) * H;
    const float* wn = Wih + (size_t)(c + 2 * H) * H;
    const float* ur = Whh + (size_t)c * H;
    const float* uz = Whh + (size_t)(c + H) * H;
    const float* un = Whh + (size_t)(c + 2 * H) * H;

    float bihr = bih[c], bihz = bih[c + H], bihn = bih[c + 2 * H];
    float bhhr = bhh[c], bhhz = bhh[c + H], bhhn = bhh[c + 2 * H];

    for (int half = 0; half < 2; half++) {
        U64 air[4] = {0,0,0,0}, aiz[4] = {0,0,0,0}, ain[4] = {0,0,0,0};
        U64 ahr[4] = {0,0,0,0}, ahz[4] = {0,0,0,0}, ahn[4] = {0,0,0,0};
        int b0 = warp * 8 + half * 4;

        #pragma unroll
        for (int k = 0; k < 8; k++) {
            int h = k * 128 + lane * 4;
            ulonglong2 wr2 = *(const ulonglong2*)(wr + h);
            ulonglong2 wz2 = *(const ulonglong2*)(wz + h);
            ulonglong2 wn2 = *(const ulonglong2*)(wn + h);
            ulonglong2 ur2 = *(const ulonglong2*)(ur + h);
            ulonglong2 uz2 = *(const ulonglong2*)(uz + h);
            ulonglong2 un2 = *(const ulonglong2*)(un + h);
            #pragma unroll
            for (int bb = 0; bb < 4; bb++) {
                int b = b0 + bb;
                ulonglong2 x2 = *(const ulonglong2*)(emb + (size_t)xrow[b] * H + h);
                ulonglong2 p2 = *(const ulonglong2*)(lh + (size_t)b * H + h);
                air[bb] = fma2(x2.x, wr2.x, air[bb]); air[bb] = fma2(x2.y, wr2.y, air[bb]);
                aiz[bb] = fma2(x2.x, wz2.x, aiz[bb]); aiz[bb] = fma2(x2.y, wz2.y, aiz[bb]);
                ain[bb] = fma2(x2.x, wn2.x, ain[bb]); ain[bb] = fma2(x2.y, wn2.y, ain[bb]);
                ahr[bb] = fma2(p2.x, ur2.x, ahr[bb]); ahr[bb] = fma2(p2.y, ur2.y, ahr[bb]);
                ahz[bb] = fma2(p2.x, uz2.x, ahz[bb]); ahz[bb] = fma2(p2.y, uz2.y, ahz[bb]);
                ahn[bb] = fma2(p2.x, un2.x, ahn[bb]); ahn[bb] = fma2(p2.y, un2.y, ahn[bb]);
            }
        }

        #pragma unroll
        for (int bb = 0; bb < 4; bb++) {
            float sir = hsum2(air[bb]), siz = hsum2(aiz[bb]), sin_ = hsum2(ain[bb]);
            float shr = hsum2(ahr[bb]), shz = hsum2(ahz[bb]), shn = hsum2(ahn[bb]);
            #pragma unroll
            for (int off = 16; off > 0; off >>= 1) {
                sir  += __shfl_down_sync(0xffffffffu, sir,  off);
                siz  += __shfl_down_sync(0xffffffffu, siz,  off);
                sin_ += __shfl_down_sync(0xffffffffu, sin_, off);
                shr  += __shfl_down_sync(0xffffffffu, shr,  off);
                shz  += __shfl_down_sync(0xffffffffu, shz,  off);
                shn  += __shfl_down_sync(0xffffffffu, shn,  off);
            }
            if (lane == 0) {
                int b = b0 + bb;
                float r = 1.0f / (1.0f + expf(-(sir + bihr + shr + bhhr)));
                float z = 1.0f / (1.0f + expf(-(siz + bihz + shz + bhhz)));
                float n = tanhf(sin_ + bihn + r * (shn + bhhn));
                float hp = lh[(size_t)b * H + c];
                float hn = (1.0f - z) * n + z * hp;
                g_hnew[(size_t)b * H + c] = hn;
                g_cat[(size_t)b * H2 + c] = hn;
                if (out_h) out_h[(size_t)b * H + c] = hn;
            }
        }
    }
}

// ---------------------------------------------------------------------------
// Kernel 2: attention pass 1 (flash-style). One warp per (b, L-chunk).
// Reads encoder_outputs exactly once; stores raw energies + online-softmax
// partial (m, s, ctx[H]) per chunk.
// ---------------------------------------------------------------------------
__global__ void attn1_kernel(const float* __restrict__ enc)
{
    int gw   = blockIdx.x * (blockDim.x >> 5) + (threadIdx.x >> 5);
    int lane = threadIdx.x & 31;
    int b    = gw >> 5;   // / CHUNKS
    int ch   = gw & 31;   // % CHUNKS

    // q in registers (32 floats / lane as 16 f32x2)
    U64 q[16];
    const float* qp = g_hnew + (size_t)b * H;
    #pragma unroll
    for (int j = 0; j < 8; j++) {
        ulonglong2 v = *(const ulonglong2*)(qp + j * 128 + lane * 4);
        q[2 * j] = v.x; q[2 * j + 1] = v.y;
    }

    U64 cacc[16];
    #pragma unroll
    for (int i = 0; i < 16; i++) cacc[i] = 0ull;
    float m = -1e30f, s = 0.0f;

    for (int li = 0; li < LC; li++) {
        int l = ch * LC + li;
        const float* ep = enc + ((size_t)l * B + b) * H;

        U64 ev[16];
        U64 ea = 0ull;
        #pragma unroll
        for (int j = 0; j < 8; j++) {
            ulonglong2 v = *(const ulonglong2*)(ep + j * 128 + lane * 4);
            ev[2 * j] = v.x; ev[2 * j + 1] = v.y;
            ea = fma2(v.x, q[2 * j], ea);
            ea = fma2(v.y, q[2 * j + 1], ea);
        }
        float e = hsum2(ea);
        #pragma unroll
        for (int off = 16; off > 0; off >>= 1)
            e += __shfl_xor_sync(0xffffffffu, e, off);

        if (lane == 0) g_energy[(size_t)b * L + l] = e;

        if (e > m) {
            float sc = expf(m - e);   // first iter: exp(-huge) = 0
            U64 sc2 = dup2(sc);
            s *= sc;
            #pragma unroll
            for (int i = 0; i < 16; i++) cacc[i] = mul2(cacc[i], sc2);
            m = e;
        }
        float p = expf(e - m);
        s += p;
        U64 pp = dup2(p);
        #pragma unroll
        for (int i = 0; i < 16; i++) cacc[i] = fma2(ev[i], pp, cacc[i]);
    }

    float* pb = g_part + (size_t)(b * CHUNKS + ch) * PS;
    #pragma unroll
    for (int j = 0; j < 8; j++) {
        ulonglong2 w;
        w.x = cacc[2 * j]; w.y = cacc[2 * j + 1];
        *(ulonglong2*)(pb + j * 128 + lane * 4) = w;
    }
    if (lane == 0) { pb[H] = m; pb[H + 1] = s; }
}

// ---------------------------------------------------------------------------
// Kernel 3: combine partials -> context; write attn_weights; copy prior.
// One block per batch.
// ---------------------------------------------------------------------------
__global__ void combine_kernel(const float* __restrict__ prior,
                               float* __restrict__ out, int write_attn)
{
    int b = blockIdx.x;
    int t = threadIdx.x;

    __shared__ float shw[CHUNKS];
    __shared__ float shM, shS;

    if (t < 32) {
        float m = g_part[(size_t)(b * CHUNKS + t) * PS + H];
        float s = g_part[(size_t)(b * CHUNKS + t) * PS + H + 1];
        float M = m;
        #pragma unroll
        for (int off = 16; off > 0; off >>= 1)
            M = fmaxf(M, __shfl_xor_sync(0xffffffffu, M, off));
        float w = expf(m - M);
        float S = s * w;
        #pragma unroll
        for (int off = 16; off > 0; off >>= 1)
            S += __shfl_xor_sync(0xffffffffu, S, off);
        shw[t] = w;
        if (t == 0) { shM = M; shS = S; }
    }
    __syncthreads();
    float M = shM, S = shS;
    float invS = 1.0f / S;

    // context: thread handles 4 h values
    {
        int h = t * 4;
        float4 acc = make_float4(0.f, 0.f, 0.f, 0.f);
        #pragma unroll 4
        for (int i = 0; i < CHUNKS; i++) {
            float4 v = *(const float4*)(g_part + (size_t)(b * CHUNKS + i) * PS + h);
            float w = shw[i];
            acc.x += w * v.x; acc.y += w * v.y;
            acc.z += w * v.z; acc.w += w * v.w;
        }
        float4 o = make_float4(acc.x * invS, acc.y * invS, acc.z * invS, acc.w * invS);
        *(float4*)(g_cat + (size_t)b * H2 + H + h) = o;
    }

    if (write_attn) {
        size_t base = (size_t)B * V + (size_t)B * H + (size_t)b * L;
        for (int l = t; l < L; l += blockDim.x)
            out[base + l] = expf(g_energy[(size_t)b * L + l] - M) * invS;
    }

    for (int p = t; p < P; p += blockDim.x)
        g_catp[(size_t)b * KO + H + p] = prior[(size_t)b * P + p];
}

// ---------------------------------------------------------------------------
// Kernel 4: concat GEMM + tanh. Block per output column c (like GRU).
// ---------------------------------------------------------------------------
__global__ void concat_kernel(const float* __restrict__ Wc,
                              const float* __restrict__ bc)
{
    int c    = blockIdx.x;
    int warp = threadIdx.x >> 5;
    int lane = threadIdx.x & 31;
    const float* w = Wc + (size_t)c * H2;
    float bias = bc[c];

    for (int half = 0; half < 2; half++) {
        U64 acc[4] = {0,0,0,0};
        int b0 = warp * 8 + half * 4;
        #pragma unroll
        for (int k = 0; k < 16; k++) {
            int h = k * 128 + lane * 4;
            ulonglong2 wv = *(const ulonglong2*)(w + h);
            #pragma unroll
            for (int bb = 0; bb < 4; bb++) {
                ulonglong2 a = *(const ulonglong2*)(g_cat + (size_t)(b0 + bb) * H2 + h);
                acc[bb] = fma2(a.x, wv.x, acc[bb]);
                acc[bb] = fma2(a.y, wv.y, acc[bb]);
            }
        }
        #pragma unroll
        for (int bb = 0; bb < 4; bb++) {
            float sv = hsum2(acc[bb]);
            #pragma unroll
            for (int off = 16; off > 0; off >>= 1)
                sv += __shfl_down_sync(0xffffffffu, sv, off);
            if (lane == 0)
                g_catp[(size_t)(b0 + bb) * KO + c] = tanhf(sv + bias);
        }
    }
}

// ---------------------------------------------------------------------------
// Kernel 5: output GEMM. Tile 128v x 64b, 128 threads, thread tile 8v x 8b.
// A staged in shared (k-major); W staged pre-duplicated as f32x2 pairs.
// ---------------------------------------------------------------------------
#define VT 128
#define KT 32

__global__ void __launch_bounds__(128)
out_gemm_kernel(const float* __restrict__ Wout,
                const float* __restrict__ bout,
                float* __restrict__ outp)
{
    __shared__ float As[KT][64];     // 8 KB
    __shared__ U64   Ws[KT][VT];     // 32 KB (each entry = {w,w})

    int vbase = blockIdx.x * VT;
    int tid   = threadIdx.x;
    int bg    = tid & 7;    // b-group: b0 = bg*8
    int vg    = tid >> 3;   // v-group: v0 = vg*8

    U64 acc[8][4];
    #pragma unroll
    for (int i = 0; i < 8; i++)
        #pragma unroll
        for (int j = 0; j < 4; j++) acc[i][j] = 0ull;

    for (int kt = 0; kt < KO; kt += KT) {
        // load A tile (512 float4 total, 4 per thread)
        #pragma unroll
        for (int i = 0; i < 4; i++) {
            int cidx = tid + i * 128;
            int b = cidx >> 3, k4 = cidx & 7;
            float4 v = *(const float4*)(g_catp + (size_t)b * KO + kt + k4 * 4);
            As[k4 * 4 + 0][b] = v.x; As[k4 * 4 + 1][b] = v.y;
            As[k4 * 4 + 2][b] = v.z; As[k4 * 4 + 3][b] = v.w;
        }
        // load W tile duplicated (1024 float4, 8 per thread)
        #pragma unroll
        for (int i = 0; i < 8; i++) {
            int cidx = tid + i * 128;
            int v = cidx >> 3, k4 = cidx & 7;
            float4 w = *(const float4*)(Wout + (size_t)(vbase + v) * KO + kt + k4 * 4);
            Ws[k4 * 4 + 0][v] = dup2(w.x); Ws[k4 * 4 + 1][v] = dup2(w.y);
            Ws[k4 * 4 + 2][v] = dup2(w.z); Ws[k4 * 4 + 3][v] = dup2(w.w);
        }
        __syncthreads();

        #pragma unroll
        for (int k = 0; k < KT; k++) {
            ulonglong2 a01 = *(const ulonglong2*)&As[k][bg * 8];
            ulonglong2 a23 = *(const ulonglong2*)&As[k][bg * 8 + 4];
            ulonglong2 w01 = *(const ulonglong2*)&Ws[k][vg * 8];
            ulonglong2 w23 = *(const ulonglong2*)&Ws[k][vg * 8 + 2];
            ulonglong2 w45 = *(const ulonglong2*)&Ws[k][vg * 8 + 4];
            ulonglong2 w67 = *(const ulonglong2*)&Ws[k][vg * 8 + 6];
            U64 wv[8] = {w01.x, w01.y, w23.x, w23.y, w45.x, w45.y, w67.x, w67.y};
            U64 a0 = a01.x, a1 = a01.y, a2 = a23.x, a3 = a23.y;
            #pragma unroll
            for (int v = 0; v < 8; v++) {
                acc[v][0] = fma2(a0, wv[v], acc[v][0]);
                acc[v][1] = fma2(a1, wv[v], acc[v][1]);
                acc[v][2] = fma2(a2, wv[v], acc[v][2]);
                acc[v][3] = fma2(a3, wv[v], acc[v][3]);
            }
        }
        __syncthreads();
    }

    #pragma unroll
    for (int v = 0; v < 8; v++) {
        int vv = vbase + vg * 8 + v;
        float bias = bout[vv];
        #pragma unroll
        for (int p = 0; p < 4; p++) {
            U64F2 t; t.u = acc[v][p];
            int b = bg * 8 + p * 2;
            outp[(size_t)b * V + vv]       = t.f.x + bias;
            outp[(size_t)(b + 1) * V + vv] = t.f.y + bias;
        }
    }
}

// ---------------------------------------------------------------------------
extern "C" void kernel_launch(void* const* d_in, const int* in_sizes, int n_in,
                              void* d_out, int out_size)
{
    const int*   seq   = (const int*)d_in[0];   // int32 (JAX x64 disabled)
    const float* lh    = (const float*)d_in[1];
    const float* enc   = (const float*)d_in[2];
    const float* prior = (const float*)d_in[3];
    const float* emb   = (const float*)d_in[4];
    const float* Wih   = (const float*)d_in[5];
    const float* Whh   = (const float*)d_in[6];
    const float* bih   = (const float*)d_in[7];
    const float* bhh   = (const float*)d_in[8];
    const float* Wc    = (const float*)d_in[9];
    const float* bc    = (const float*)d_in[10];
    const float* Wout  = (const float*)d_in[11];
    const float* bout  = (const float*)d_in[12];

    float* out = (float*)d_out;
    long long need_h    = (long long)B * V + (long long)B * H;
    long long need_attn = need_h + (long long)B * L;
    float* out_h = ((long long)out_size >= need_h) ? out + (size_t)B * V : nullptr;
    int write_attn = ((long long)out_size >= need_attn) ? 1 : 0;

    gru_kernel<<<H, 256>>>(seq, lh, emb, Wih, Whh, bih, bhh, out_h);
    attn1_kernel<<<(B * CHUNKS) / 4, 128>>>(enc);
    combine_kernel<<<B, 256>>>(prior, out, write_attn);
    concat_kernel<<<H, 256>>>(Wc, bc);
    out_gemm_kernel<<<V / VT, 128>>>(Wout, bout, out);
}

// round 3
// speedup vs baseline: 1.4147x; 1.4147x over previous
#include <cuda_runtime.h>
#include <cuda_bf16.h>
#include <math.h>

// Problem constants
#define B  64
#define L  2048
#define H  1024
#define V  32000
#define P  128
#define H2 2048          // 2*H
#define KO 1152          // H + P

#define CHUNKS 32        // L-splits for attention
#define LC (L / CHUNKS)  // 64
#define PS (H + 4)       // partial stride (16B aligned)

typedef unsigned long long U64;

union U64F2 { U64 u; float2 f; };

__device__ __forceinline__ U64 fma2(U64 a, U64 b, U64 c) {
    U64 d;
    asm("fma.rn.f32x2 %0, %1, %2, %3;" : "=l"(d) : "l"(a), "l"(b), "l"(c));
    return d;
}
__device__ __forceinline__ U64 mul2(U64 a, U64 b) {
    U64 d;
    asm("mul.rn.f32x2 %0, %1, %2;" : "=l"(d) : "l"(a), "l"(b));
    return d;
}
__device__ __forceinline__ float hsum2(U64 a) {
    U64F2 t; t.u = a; return t.f.x + t.f.y;
}
__device__ __forceinline__ U64 dup2(float x) {
    U64F2 t; t.f.x = x; t.f.y = x; return t.u;
}
__device__ __forceinline__ U64 pack2(float x, float y) {
    U64F2 t; t.f.x = x; t.f.y = y; return t.u;
}

// Scratch (device globals — no allocation allowed)
__device__ float g_x[B * H];                    // gathered embeddings
__device__ float g_hnew[B * H];
__device__ float g_cat[B * H2];                 // [h_new | context]
__device__ float g_catp[B * KO];                // [concat_out | prior]
__device__ float g_energy[B * L];
__device__ float g_part[B * CHUNKS * PS];       // ctx partial + (m, s)
__device__ float g_pih[4 * B * 3 * H];          // GRU ih partials (ksplit=4)
__device__ float g_phh[4 * B * 3 * H];          // GRU hh partials
__device__ float g_pcc[16 * B * H];             // concat partials (ksplit=16)

// ---------------------------------------------------------------------------
// Kernel 0: gather x = emb[seq]
// ---------------------------------------------------------------------------
__global__ void gather_x_kernel(const int* __restrict__ seq,
                                const float* __restrict__ emb)
{
    int b = blockIdx.x;
    int j = threadIdx.x;           // 256 threads, 4 floats each
    float4 v = *(const float4*)(emb + (size_t)seq[b] * H + j * 4);
    *(float4*)(g_x + (size_t)b * H + j * 4) = v;
}

// ---------------------------------------------------------------------------
// Unified GEMM: C[b,n] = sum_k A[b,k] * W[n,k]   (A: [64,K], W: [N,K])
// Tile: 128n x 64b, 256 threads, thread-tile 8n x 4b.
// Even/odd k accumulated in the two f32x2 lanes (no operand duplication).
// grid = (N/128, ksplit, nsel). blockIdx.z selects (A0,W0,C0) vs (A1,W1,C1).
// bias != null  -> final output, row stride ldc.
// bias == null  -> partial output at C + blockIdx.y*64*ldc (ldc = N).
// ---------------------------------------------------------------------------
#define GKT 32

__global__ void __launch_bounds__(256)
gemm_kernel(const float* __restrict__ A0, const float* __restrict__ A1,
            const float* __restrict__ W0, const float* __restrict__ W1,
            float* __restrict__ C0, float* __restrict__ C1,
            const float* __restrict__ bias,
            int N, int K, int ksplit, int ldc)
{
    __shared__ U64 As2[16][66];    // [k-pair][b], padded stride (16B-aligned)
    __shared__ U64 Ws2[16][130];   // [k-pair][n]

    const float* A = blockIdx.z ? A1 : A0;
    const float* W = blockIdx.z ? W1 : W0;
    float*       C = blockIdx.z ? C1 : C0;

    int vbase = blockIdx.x * 128;
    int kc    = K / ksplit;
    int k0    = blockIdx.y * kc;
    int tiles = kc / GKT;

    int tid = threadIdx.x;
    int vg  = tid >> 4;     // 0..15 -> n-group of 8
    int bg  = tid & 15;     // 0..15 -> b-group of 4
    int r8  = tid >> 3;     // 0..31
    int k4  = tid & 7;      // float4 index within 32-k tile

    U64 acc[8][4];
    #pragma unroll
    for (int v = 0; v < 8; v++)
        #pragma unroll
        for (int j = 0; j < 4; j++) acc[v][j] = 0ull;

    float4 pa[2], pw[4];
    // prefetch tile 0
    {
        int kt = k0 + k4 * 4;
        #pragma unroll
        for (int i = 0; i < 2; i++)
            pa[i] = *(const float4*)(A + (size_t)(r8 + i * 32) * K + kt);
        #pragma unroll
        for (int i = 0; i < 4; i++)
            pw[i] = *(const float4*)(W + (size_t)(vbase + r8 + i * 32) * K + kt);
    }

    for (int t = 0; t < tiles; t++) {
        __syncthreads();
        #pragma unroll
        for (int i = 0; i < 2; i++) {
            int b = r8 + i * 32;
            As2[2 * k4][b]     = pack2(pa[i].x, pa[i].y);
            As2[2 * k4 + 1][b] = pack2(pa[i].z, pa[i].w);
        }
        #pragma unroll
        for (int i = 0; i < 4; i++) {
            int n = r8 + i * 32;
            Ws2[2 * k4][n]     = pack2(pw[i].x, pw[i].y);
            Ws2[2 * k4 + 1][n] = pack2(pw[i].z, pw[i].w);
        }
        __syncthreads();

        if (t + 1 < tiles) {
            int kt = k0 + (t + 1) * GKT + k4 * 4;
            #pragma unroll
            for (int i = 0; i < 2; i++)
                pa[i] = *(const float4*)(A + (size_t)(r8 + i * 32) * K + kt);
            #pragma unroll
            for (int i = 0; i < 4; i++)
                pw[i] = *(const float4*)(W + (size_t)(vbase + r8 + i * 32) * K + kt);
        }

        #pragma unroll
        for (int kp = 0; kp < 16; kp++) {
            ulonglong2 a01 = *(const ulonglong2*)&As2[kp][bg * 4];
            ulonglong2 a23 = *(const ulonglong2*)&As2[kp][bg * 4 + 2];
            ulonglong2 w01 = *(const ulonglong2*)&Ws2[kp][vg * 8];
            ulonglong2 w23 = *(const ulonglong2*)&Ws2[kp][vg * 8 + 2];
            ulonglong2 w45 = *(const ulonglong2*)&Ws2[kp][vg * 8 + 4];
            ulonglong2 w67 = *(const ulonglong2*)&Ws2[kp][vg * 8 + 6];
            U64 a[4] = {a01.x, a01.y, a23.x, a23.y};
            U64 w[8] = {w01.x, w01.y, w23.x, w23.y, w45.x, w45.y, w67.x, w67.y};
            #pragma unroll
            for (int v = 0; v < 8; v++) {
                acc[v][0] = fma2(a[0], w[v], acc[v][0]);
                acc[v][1] = fma2(a[1], w[v], acc[v][1]);
                acc[v][2] = fma2(a[2], w[v], acc[v][2]);
                acc[v][3] = fma2(a[3], w[v], acc[v][3]);
            }
        }
    }

    // epilogue
    float bv[8];
    #pragma unroll
    for (int v = 0; v < 8; v++)
        bv[v] = bias ? bias[vbase + vg * 8 + v] : 0.0f;

    float* Cb = bias ? C : (C + (size_t)blockIdx.y * 64 * ldc);
    #pragma unroll
    for (int j = 0; j < 4; j++) {
        int b = bg * 4 + j;
        float4 o0, o1;
        o0.x = hsum2(acc[0][j]) + bv[0];
        o0.y = hsum2(acc[1][j]) + bv[1];
        o0.z = hsum2(acc[2][j]) + bv[2];
        o0.w = hsum2(acc[3][j]) + bv[3];
        o1.x = hsum2(acc[4][j]) + bv[4];
        o1.y = hsum2(acc[5][j]) + bv[5];
        o1.z = hsum2(acc[6][j]) + bv[6];
        o1.w = hsum2(acc[7][j]) + bv[7];
        float* cp = Cb + (size_t)b * ldc + vbase + vg * 8;
        *(float4*)cp       = o0;
        *(float4*)(cp + 4) = o1;
    }
}

// ---------------------------------------------------------------------------
// GRU gates: reduce ksplit=4 partials of gi/gh, apply gate math.
// ---------------------------------------------------------------------------
__global__ void gru_gates_kernel(const float* __restrict__ lh,
                                 const float* __restrict__ bih,
                                 const float* __restrict__ bhh,
                                 float* __restrict__ out_h)
{
    int idx = blockIdx.x * 256 + threadIdx.x;   // 0..65535
    int b = idx >> 10;
    int c = idx & 1023;

    float gir = 0.f, giz = 0.f, gin = 0.f, ghr = 0.f, ghz = 0.f, ghn = 0.f;
    #pragma unroll
    for (int s = 0; s < 4; s++) {
        size_t base = ((size_t)(s * 64 + b)) * (3 * H) + c;
        gir += g_pih[base];
        giz += g_pih[base + H];
        gin += g_pih[base + 2 * H];
        ghr += g_phh[base];
        ghz += g_phh[base + H];
        ghn += g_phh[base + 2 * H];
    }
    gir += bih[c]; giz += bih[c + H]; gin += bih[c + 2 * H];
    ghr += bhh[c]; ghz += bhh[c + H]; ghn += bhh[c + 2 * H];

    float r = 1.0f / (1.0f + expf(-(gir + ghr)));
    float z = 1.0f / (1.0f + expf(-(giz + ghz)));
    float n = tanhf(gin + r * ghn);
    float hp = lh[(size_t)b * H + c];
    float hn = (1.0f - z) * n + z * hp;

    g_hnew[(size_t)b * H + c] = hn;
    g_cat[(size_t)b * H2 + c] = hn;
    if (out_h) out_h[(size_t)b * H + c] = hn;
}

// ---------------------------------------------------------------------------
// concat reduce: sum ksplit=16 partials + bias, tanh -> g_catp
// ---------------------------------------------------------------------------
__global__ void creduce_kernel(const float* __restrict__ bc)
{
    int idx = blockIdx.x * 256 + threadIdx.x;
    int b = idx >> 10;
    int c = idx & 1023;
    float s = 0.f;
    #pragma unroll
    for (int k = 0; k < 16; k++)
        s += g_pcc[((size_t)(k * 64 + b)) * H + c];
    g_catp[(size_t)b * KO + c] = tanhf(s + bc[c]);
}

// ---------------------------------------------------------------------------
// Attention pass 1 (flash-style, software pipelined). One warp per (b, chunk).
// ---------------------------------------------------------------------------
__device__ __forceinline__ void attn_load(U64* ev, const float* __restrict__ enc,
                                          int l, int b, int lane)
{
    const float* ep = enc + ((size_t)l * B + b) * H;
    #pragma unroll
    for (int j = 0; j < 8; j++) {
        ulonglong2 v = *(const ulonglong2*)(ep + j * 128 + lane * 4);
        ev[2 * j] = v.x; ev[2 * j + 1] = v.y;
    }
}

__global__ void attn1_kernel(const float* __restrict__ enc)
{
    int gw   = blockIdx.x * (blockDim.x >> 5) + (threadIdx.x >> 5);
    int lane = threadIdx.x & 31;
    int b    = gw >> 5;   // / CHUNKS
    int ch   = gw & 31;   // % CHUNKS
    int l0   = ch * LC;

    U64 q[16];
    const float* qp = g_hnew + (size_t)b * H;
    #pragma unroll
    for (int j = 0; j < 8; j++) {
        ulonglong2 v = *(const ulonglong2*)(qp + j * 128 + lane * 4);
        q[2 * j] = v.x; q[2 * j + 1] = v.y;
    }

    U64 cacc[16];
    #pragma unroll
    for (int i = 0; i < 16; i++) cacc[i] = 0ull;
    float m = -1e30f, s = 0.0f;

    U64 eva[16], evb[16];
    attn_load(eva, enc, l0, b, lane);

    #pragma unroll 1
    for (int li = 0; li < LC; li += 2) {
        // prefetch li+1 while processing li
        attn_load(evb, enc, l0 + li + 1, b, lane);

        {   // process eva (l = l0+li)
            U64 ea = 0ull;
            #pragma unroll
            for (int i = 0; i < 16; i++) ea = fma2(eva[i], q[i], ea);
            float e = hsum2(ea);
            #pragma unroll
            for (int off = 16; off > 0; off >>= 1)
                e += __shfl_xor_sync(0xffffffffu, e, off);
            if (lane == 0) g_energy[(size_t)b * L + l0 + li] = e;
            if (e > m) {
                float sc = expf(m - e);
                U64 sc2 = dup2(sc);
                s *= sc;
                #pragma unroll
                for (int i = 0; i < 16; i++) cacc[i] = mul2(cacc[i], sc2);
                m = e;
            }
            float p = expf(e - m);
            s += p;
            U64 pp = dup2(p);
            #pragma unroll
            for (int i = 0; i < 16; i++) cacc[i] = fma2(eva[i], pp, cacc[i]);
        }

        if (li + 2 < LC) attn_load(eva, enc, l0 + li + 2, b, lane);

        {   // process evb (l = l0+li+1)
            U64 ea = 0ull;
            #pragma unroll
            for (int i = 0; i < 16; i++) ea = fma2(evb[i], q[i], ea);
            float e = hsum2(ea);
            #pragma unroll
            for (int off = 16; off > 0; off >>= 1)
                e += __shfl_xor_sync(0xffffffffu, e, off);
            if (lane == 0) g_energy[(size_t)b * L + l0 + li + 1] = e;
            if (e > m) {
                float sc = expf(m - e);
                U64 sc2 = dup2(sc);
                s *= sc;
                #pragma unroll
                for (int i = 0; i < 16; i++) cacc[i] = mul2(cacc[i], sc2);
                m = e;
            }
            float p = expf(e - m);
            s += p;
            U64 pp = dup2(p);
            #pragma unroll
            for (int i = 0; i < 16; i++) cacc[i] = fma2(evb[i], pp, cacc[i]);
        }
    }

    float* pb = g_part + (size_t)(b * CHUNKS + ch) * PS;
    #pragma unroll
    for (int j = 0; j < 8; j++) {
        ulonglong2 w;
        w.x = cacc[2 * j]; w.y = cacc[2 * j + 1];
        *(ulonglong2*)(pb + j * 128 + lane * 4) = w;
    }
    if (lane == 0) { pb[H] = m; pb[H + 1] = s; }
}

// ---------------------------------------------------------------------------
// Combine partials -> context; write attn_weights; copy prior into g_catp.
// ---------------------------------------------------------------------------
__global__ void combine_kernel(const float* __restrict__ prior,
                               float* __restrict__ out, int write_attn)
{
    int b = blockIdx.x;
    int t = threadIdx.x;

    __shared__ float shw[CHUNKS];
    __shared__ float shM, shS;

    if (t < 32) {
        float m = g_part[(size_t)(b * CHUNKS + t) * PS + H];
        float s = g_part[(size_t)(b * CHUNKS + t) * PS + H + 1];
        float M = m;
        #pragma unroll
        for (int off = 16; off > 0; off >>= 1)
            M = fmaxf(M, __shfl_xor_sync(0xffffffffu, M, off));
        float w = expf(m - M);
        float S = s * w;
        #pragma unroll
        for (int off = 16; off > 0; off >>= 1)
            S += __shfl_xor_sync(0xffffffffu, S, off);
        shw[t] = w;
        if (t == 0) { shM = M; shS = S; }
    }
    __syncthreads();
    float M = shM, S = shS;
    float invS = 1.0f / S;

    {
        int h = t * 4;
        float4 acc = make_float4(0.f, 0.f, 0.f, 0.f);
        #pragma unroll 4
        for (int i = 0; i < CHUNKS; i++) {
            float4 v = *(const float4*)(g_part + (size_t)(b * CHUNKS + i) * PS + h);
            float w = shw[i];
            acc.x += w * v.x; acc.y += w * v.y;
            acc.z += w * v.z; acc.w += w * v.w;
        }
        float4 o = make_float4(acc.x * invS, acc.y * invS, acc.z * invS, acc.w * invS);
        *(float4*)(g_cat + (size_t)b * H2 + H + h) = o;
    }

    if (write_attn) {
        size_t base = (size_t)B * V + (size_t)B * H + (size_t)b * L;
        for (int l = t; l < L; l += blockDim.x)
            out[base + l] = expf(g_energy[(size_t)b * L + l] - M) * invS;
    }

    for (int p = t; p < P; p += blockDim.x)
        g_catp[(size_t)b * KO + H + p] = prior[(size_t)b * P + p];
}

// ---------------------------------------------------------------------------
extern "C" void kernel_launch(void* const* d_in, const int* in_sizes, int n_in,
                              void* d_out, int out_size)
{
    const int*   seq   = (const int*)d_in[0];   // int32 (JAX x64 disabled)
    const float* lh    = (const float*)d_in[1];
    const float* enc   = (const float*)d_in[2];
    const float* prior = (const float*)d_in[3];
    const float* emb   = (const float*)d_in[4];
    const float* Wih   = (const float*)d_in[5];
    const float* Whh   = (const float*)d_in[6];
    const float* bih   = (const float*)d_in[7];
    const float* bhh   = (const float*)d_in[8];
    const float* Wc    = (const float*)d_in[9];
    const float* bc    = (const float*)d_in[10];
    const float* Wout  = (const float*)d_in[11];
    const float* bout  = (const float*)d_in[12];

    float* out = (float*)d_out;
    long long need_h    = (long long)B * V + (long long)B * H;
    long long need_attn = need_h + (long long)B * L;
    float* out_h = ((long long)out_size >= need_h) ? out + (size_t)B * V : nullptr;
    int write_attn = ((long long)out_size >= need_attn) ? 1 : 0;

    float* pih; cudaGetSymbolAddress((void**)&pih, g_pih);
    float* phh; cudaGetSymbolAddress((void**)&phh, g_phh);
    float* pcc; cudaGetSymbolAddress((void**)&pcc, g_pcc);
    float* gx;  cudaGetSymbolAddress((void**)&gx,  g_x);
    float* gcat; cudaGetSymbolAddress((void**)&gcat, g_cat);
    float* gcatp; cudaGetSymbolAddress((void**)&gcatp, g_catp);

    // 1. gather x = emb[seq]
    gather_x_kernel<<<B, 256>>>(seq, emb);

    // 2. GRU GEMMs: gi = x@Wih^T, gh = h@Whh^T   (N=3072, K=1024, ksplit=4)
    gemm_kernel<<<dim3(3 * H / 128, 4, 2), 256>>>(
        gx, lh, Wih, Whh, pih, phh, nullptr, 3 * H, H, 4, 3 * H);

    // 3. gates -> h_new
    gru_gates_kernel<<<B * H / 256, 256>>>(lh, bih, bhh, out_h);

    // 4. flash attention over encoder_outputs (read once)
    attn1_kernel<<<(B * CHUNKS) / 4, 128>>>(enc);

    // 5. combine -> context, attn weights, prior copy
    combine_kernel<<<B, 256>>>(prior, out, write_attn);

    // 6. concat GEMM (N=1024, K=2048, ksplit=16) + reduce/tanh
    gemm_kernel<<<dim3(H / 128, 16, 1), 256>>>(
        gcat, gcat, Wc, Wc, pcc, pcc, nullptr, H, H2, 16, H);
    creduce_kernel<<<B * H / 256, 256>>>(bc);

    // 7. output GEMM (N=32000, K=1152, bias)
    gemm_kernel<<<dim3(V / 128, 1, 1), 256>>>(
        gcatp, gcatp, Wout, Wout, out, out, bout, V, KO, 1, V);
}

// round 4
// speedup vs baseline: 1.4921x; 1.0547x over previous
#include <cuda_runtime.h>
#include <cuda_bf16.h>
#include <math.h>

// Problem constants
#define B  64
#define L  2048
#define H  1024
#define V  32000
#define P  128
#define H2 2048          // 2*H
#define KO 1152          // H + P

#define CHUNKS 64        // L-splits for attention
#define LC (L / CHUNKS)  // 32
#define PS (H + 4)       // partial stride (16B aligned)

typedef unsigned long long U64;

union U64F2 { U64 u; float2 f; };

__device__ __forceinline__ U64 fma2(U64 a, U64 b, U64 c) {
    U64 d;
    asm("fma.rn.f32x2 %0, %1, %2, %3;" : "=l"(d) : "l"(a), "l"(b), "l"(c));
    return d;
}
__device__ __forceinline__ U64 mul2(U64 a, U64 b) {
    U64 d;
    asm("mul.rn.f32x2 %0, %1, %2;" : "=l"(d) : "l"(a), "l"(b));
    return d;
}
__device__ __forceinline__ float hsum2(U64 a) {
    U64F2 t; t.u = a; return t.f.x + t.f.y;
}
__device__ __forceinline__ U64 dup2(float x) {
    U64F2 t; t.f.x = x; t.f.y = x; return t.u;
}
__device__ __forceinline__ U64 pack2(float x, float y) {
    U64F2 t; t.f.x = x; t.f.y = y; return t.u;
}

// Scratch (device globals — no allocation allowed)
__device__ float g_x[B * H];                    // gathered embeddings
__device__ float g_hnew[B * H];
__device__ float g_cat[B * H2];                 // [h_new | context]
__device__ float g_catp[B * KO];                // [concat_out | prior]
__device__ float g_energy[B * L];
__device__ float g_part[B * CHUNKS * PS];       // ctx partial + (m, s)
__device__ float g_pih[4 * B * 3 * H];          // GRU ih partials (ksplit=4)
__device__ float g_phh[4 * B * 3 * H];          // GRU hh partials
__device__ float g_pcc[16 * B * H];             // concat partials (ksplit=16)

// ---------------------------------------------------------------------------
// Kernel 0: gather x = emb[seq]
// ---------------------------------------------------------------------------
__global__ void gather_x_kernel(const int* __restrict__ seq,
                                const float* __restrict__ emb)
{
    int b = blockIdx.x;
    int j = threadIdx.x;           // 256 threads, 4 floats each
    float4 v = *(const float4*)(emb + (size_t)seq[b] * H + j * 4);
    *(float4*)(g_x + (size_t)b * H + j * 4) = v;
}

// ---------------------------------------------------------------------------
// Unified GEMM: C[b,n] = sum_k A[b,k] * W[n,k]   (A: [64,K], W: [N,K])
// Tile: 128n x 64b, 256 threads, thread-tile 8n x 4b.
// Even/odd k accumulated in the two f32x2 lanes.
// grid = (N/128, ksplit, nsel). blockIdx.z selects (A0,W0,C0) vs (A1,W1,C1).
// ---------------------------------------------------------------------------
#define GKT 32

__global__ void __launch_bounds__(256, 2)
gemm_kernel(const float* __restrict__ A0, const float* __restrict__ A1,
            const float* __restrict__ W0, const float* __restrict__ W1,
            float* __restrict__ C0, float* __restrict__ C1,
            const float* __restrict__ bias,
            int N, int K, int ksplit, int ldc)
{
    __shared__ U64 As2[16][66];    // [k-pair][b], padded stride (16B-aligned)
    __shared__ U64 Ws2[16][130];   // [k-pair][n]

    const float* A = blockIdx.z ? A1 : A0;
    const float* W = blockIdx.z ? W1 : W0;
    float*       C = blockIdx.z ? C1 : C0;

    int vbase = blockIdx.x * 128;
    int kc    = K / ksplit;
    int k0    = blockIdx.y * kc;
    int tiles = kc / GKT;

    int tid = threadIdx.x;
    int vg  = tid >> 4;     // 0..15 -> n-group of 8
    int bg  = tid & 15;     // 0..15 -> b-group of 4
    int r8  = tid >> 3;     // 0..31
    int k4  = tid & 7;      // float4 index within 32-k tile

    U64 acc[8][4];
    #pragma unroll
    for (int v = 0; v < 8; v++)
        #pragma unroll
        for (int j = 0; j < 4; j++) acc[v][j] = 0ull;

    float4 pa[2], pw[4];
    // prefetch tile 0
    {
        int kt = k0 + k4 * 4;
        #pragma unroll
        for (int i = 0; i < 2; i++)
            pa[i] = *(const float4*)(A + (size_t)(r8 + i * 32) * K + kt);
        #pragma unroll
        for (int i = 0; i < 4; i++)
            pw[i] = *(const float4*)(W + (size_t)(vbase + r8 + i * 32) * K + kt);
    }

    for (int t = 0; t < tiles; t++) {
        __syncthreads();
        #pragma unroll
        for (int i = 0; i < 2; i++) {
            int b = r8 + i * 32;
            As2[2 * k4][b]     = pack2(pa[i].x, pa[i].y);
            As2[2 * k4 + 1][b] = pack2(pa[i].z, pa[i].w);
        }
        #pragma unroll
        for (int i = 0; i < 4; i++) {
            int n = r8 + i * 32;
            Ws2[2 * k4][n]     = pack2(pw[i].x, pw[i].y);
            Ws2[2 * k4 + 1][n] = pack2(pw[i].z, pw[i].w);
        }
        __syncthreads();

        if (t + 1 < tiles) {
            int kt = k0 + (t + 1) * GKT + k4 * 4;
            #pragma unroll
            for (int i = 0; i < 2; i++)
                pa[i] = *(const float4*)(A + (size_t)(r8 + i * 32) * K + kt);
            #pragma unroll
            for (int i = 0; i < 4; i++)
                pw[i] = *(const float4*)(W + (size_t)(vbase + r8 + i * 32) * K + kt);
        }

        #pragma unroll
        for (int kp = 0; kp < 16; kp++) {
            ulonglong2 a01 = *(const ulonglong2*)&As2[kp][bg * 4];
            ulonglong2 a23 = *(const ulonglong2*)&As2[kp][bg * 4 + 2];
            ulonglong2 w01 = *(const ulonglong2*)&Ws2[kp][vg * 8];
            ulonglong2 w23 = *(const ulonglong2*)&Ws2[kp][vg * 8 + 2];
            ulonglong2 w45 = *(const ulonglong2*)&Ws2[kp][vg * 8 + 4];
            ulonglong2 w67 = *(const ulonglong2*)&Ws2[kp][vg * 8 + 6];
            U64 a[4] = {a01.x, a01.y, a23.x, a23.y};
            U64 w[8] = {w01.x, w01.y, w23.x, w23.y, w45.x, w45.y, w67.x, w67.y};
            #pragma unroll
            for (int v = 0; v < 8; v++) {
                acc[v][0] = fma2(a[0], w[v], acc[v][0]);
                acc[v][1] = fma2(a[1], w[v], acc[v][1]);
                acc[v][2] = fma2(a[2], w[v], acc[v][2]);
                acc[v][3] = fma2(a[3], w[v], acc[v][3]);
            }
        }
    }

    // epilogue
    float bv[8];
    #pragma unroll
    for (int v = 0; v < 8; v++)
        bv[v] = bias ? bias[vbase + vg * 8 + v] : 0.0f;

    float* Cb = bias ? C : (C + (size_t)blockIdx.y * 64 * ldc);
    #pragma unroll
    for (int j = 0; j < 4; j++) {
        int b = bg * 4 + j;
        float4 o0, o1;
        o0.x = hsum2(acc[0][j]) + bv[0];
        o0.y = hsum2(acc[1][j]) + bv[1];
        o0.z = hsum2(acc[2][j]) + bv[2];
        o0.w = hsum2(acc[3][j]) + bv[3];
        o1.x = hsum2(acc[4][j]) + bv[4];
        o1.y = hsum2(acc[5][j]) + bv[5];
        o1.z = hsum2(acc[6][j]) + bv[6];
        o1.w = hsum2(acc[7][j]) + bv[7];
        float* cp = Cb + (size_t)b * ldc + vbase + vg * 8;
        *(float4*)cp       = o0;
        *(float4*)(cp + 4) = o1;
    }
}

// ---------------------------------------------------------------------------
// GRU gates: reduce ksplit=4 partials of gi/gh, apply gate math.
// ---------------------------------------------------------------------------
__global__ void gru_gates_kernel(const float* __restrict__ lh,
                                 const float* __restrict__ bih,
                                 const float* __restrict__ bhh,
                                 float* __restrict__ out_h)
{
    int idx = blockIdx.x * 256 + threadIdx.x;   // 0..65535
    int b = idx >> 10;
    int c = idx & 1023;

    float gir = 0.f, giz = 0.f, gin = 0.f, ghr = 0.f, ghz = 0.f, ghn = 0.f;
    #pragma unroll
    for (int s = 0; s < 4; s++) {
        size_t base = ((size_t)(s * 64 + b)) * (3 * H) + c;
        gir += g_pih[base];
        giz += g_pih[base + H];
        gin += g_pih[base + 2 * H];
        ghr += g_phh[base];
        ghz += g_phh[base + H];
        ghn += g_phh[base + 2 * H];
    }
    gir += bih[c]; giz += bih[c + H]; gin += bih[c + 2 * H];
    ghr += bhh[c]; ghz += bhh[c + H]; ghn += bhh[c + 2 * H];

    float r = 1.0f / (1.0f + expf(-(gir + ghr)));
    float z = 1.0f / (1.0f + expf(-(giz + ghz)));
    float n = tanhf(gin + r * ghn);
    float hp = lh[(size_t)b * H + c];
    float hn = (1.0f - z) * n + z * hp;

    g_hnew[(size_t)b * H + c] = hn;
    g_cat[(size_t)b * H2 + c] = hn;
    if (out_h) out_h[(size_t)b * H + c] = hn;
}

// ---------------------------------------------------------------------------
// concat reduce: sum ksplit=16 partials + bias, tanh -> g_catp
// ---------------------------------------------------------------------------
__global__ void creduce_kernel(const float* __restrict__ bc)
{
    int idx = blockIdx.x * 256 + threadIdx.x;
    int b = idx >> 10;
    int c = idx & 1023;
    float s = 0.f;
    #pragma unroll
    for (int k = 0; k < 16; k++)
        s += g_pcc[((size_t)(k * 64 + b)) * H + c];
    g_catp[(size_t)b * KO + c] = tanhf(s + bc[c]);
}

// ---------------------------------------------------------------------------
// Attention pass 1 (flash-style). One warp per (b, chunk). Rows processed in
// pairs: interleaved loads (2x MLP), interleaved shuffle reductions, single
// joint max/rescale per pair.
// ---------------------------------------------------------------------------
__global__ void __launch_bounds__(128)
attn1_kernel(const float* __restrict__ enc)
{
    int gw   = blockIdx.x * (blockDim.x >> 5) + (threadIdx.x >> 5);
    int lane = threadIdx.x & 31;
    int b    = gw >> 6;     // / CHUNKS
    int ch   = gw & 63;     // % CHUNKS
    int l0   = ch * LC;

    U64 q[16];
    const float* qp = g_hnew + (size_t)b * H;
    #pragma unroll
    for (int j = 0; j < 8; j++) {
        ulonglong2 v = *(const ulonglong2*)(qp + j * 128 + lane * 4);
        q[2 * j] = v.x; q[2 * j + 1] = v.y;
    }

    U64 cacc[16];
    #pragma unroll
    for (int i = 0; i < 16; i++) cacc[i] = 0ull;
    float m = -1e30f, s = 0.0f;

    #pragma unroll 1
    for (int li = 0; li < LC; li += 2) {
        const float* ep0 = enc + ((size_t)(l0 + li) * B + b) * H + lane * 4;
        const float* ep1 = ep0 + (size_t)B * H;

        U64 ev0[16], ev1[16];
        // interleaved loads: 16 LDG.128 in flight
        #pragma unroll
        for (int j = 0; j < 8; j++) {
            ulonglong2 v0 = *(const ulonglong2*)(ep0 + j * 128);
            ulonglong2 v1 = *(const ulonglong2*)(ep1 + j * 128);
            ev0[2 * j] = v0.x; ev0[2 * j + 1] = v0.y;
            ev1[2 * j] = v1.x; ev1[2 * j + 1] = v1.y;
        }

        // two independent dot chains
        U64 ea0 = 0ull, ea1 = 0ull;
        #pragma unroll
        for (int i = 0; i < 16; i++) {
            ea0 = fma2(ev0[i], q[i], ea0);
            ea1 = fma2(ev1[i], q[i], ea1);
        }
        float e0 = hsum2(ea0);
        float e1 = hsum2(ea1);
        #pragma unroll
        for (int off = 16; off > 0; off >>= 1) {
            e0 += __shfl_xor_sync(0xffffffffu, e0, off);
            e1 += __shfl_xor_sync(0xffffffffu, e1, off);
        }

        if (lane == 0) {
            g_energy[(size_t)b * L + l0 + li]     = e0;
            g_energy[(size_t)b * L + l0 + li + 1] = e1;
        }

        float mn = fmaxf(m, fmaxf(e0, e1));
        float sc = expf(m - mn);      // first pair: exp(-huge) = 0
        float p0 = expf(e0 - mn);
        float p1 = expf(e1 - mn);
        s = s * sc + p0 + p1;
        m = mn;
        U64 sc2 = dup2(sc), pp0 = dup2(p0), pp1 = dup2(p1);
        #pragma unroll
        for (int i = 0; i < 16; i++) {
            U64 t = mul2(cacc[i], sc2);
            t = fma2(ev0[i], pp0, t);
            cacc[i] = fma2(ev1[i], pp1, t);
        }
    }

    float* pb = g_part + (size_t)(b * CHUNKS + ch) * PS;
    #pragma unroll
    for (int j = 0; j < 8; j++) {
        ulonglong2 w;
        w.x = cacc[2 * j]; w.y = cacc[2 * j + 1];
        *(ulonglong2*)(pb + j * 128 + lane * 4) = w;
    }
    if (lane == 0) { pb[H] = m; pb[H + 1] = s; }
}

// ---------------------------------------------------------------------------
// Combine partials -> context; write attn_weights; copy prior into g_catp.
// One block (256 thr) per batch; CHUNKS=64 partials.
// ---------------------------------------------------------------------------
__global__ void combine_kernel(const float* __restrict__ prior,
                               float* __restrict__ out, int write_attn)
{
    int b = blockIdx.x;
    int t = threadIdx.x;

    __shared__ float shm[CHUNKS], shs[CHUNKS], shw[CHUNKS];
    __shared__ float shM, shS;

    if (t < CHUNKS) {
        shm[t] = g_part[(size_t)(b * CHUNKS + t) * PS + H];
        shs[t] = g_part[(size_t)(b * CHUNKS + t) * PS + H + 1];
    }
    __syncthreads();
    if (t < 32) {
        float M = fmaxf(shm[t], shm[t + 32]);
        #pragma unroll
        for (int off = 16; off > 0; off >>= 1)
            M = fmaxf(M, __shfl_xor_sync(0xffffffffu, M, off));
        if (t == 0) shM = M;
    }
    __syncthreads();
    float M = shM;
    if (t < CHUNKS) shw[t] = expf(shm[t] - M);
    __syncthreads();
    if (t < 32) {
        float S = shs[t] * shw[t] + shs[t + 32] * shw[t + 32];
        #pragma unroll
        for (int off = 16; off > 0; off >>= 1)
            S += __shfl_xor_sync(0xffffffffu, S, off);
        if (t == 0) shS = S;
    }
    __syncthreads();
    float invS = 1.0f / shS;

    {
        int h = t * 4;
        float4 acc = make_float4(0.f, 0.f, 0.f, 0.f);
        #pragma unroll 4
        for (int i = 0; i < CHUNKS; i++) {
            float4 v = *(const float4*)(g_part + (size_t)(b * CHUNKS + i) * PS + h);
            float w = shw[i];
            acc.x += w * v.x; acc.y += w * v.y;
            acc.z += w * v.z; acc.w += w * v.w;
        }
        float4 o = make_float4(acc.x * invS, acc.y * invS, acc.z * invS, acc.w * invS);
        *(float4*)(g_cat + (size_t)b * H2 + H + h) = o;
    }

    if (write_attn) {
        size_t base = (size_t)B * V + (size_t)B * H + (size_t)b * L;
        for (int l = t; l < L; l += blockDim.x)
            out[base + l] = expf(g_energy[(size_t)b * L + l] - M) * invS;
    }

    for (int p = t; p < P; p += blockDim.x)
        g_catp[(size_t)b * KO + H + p] = prior[(size_t)b * P + p];
}

// ---------------------------------------------------------------------------
extern "C" void kernel_launch(void* const* d_in, const int* in_sizes, int n_in,
                              void* d_out, int out_size)
{
    const int*   seq   = (const int*)d_in[0];   // int32 (JAX x64 disabled)
    const float* lh    = (const float*)d_in[1];
    const float* enc   = (const float*)d_in[2];
    const float* prior = (const float*)d_in[3];
    const float* emb   = (const float*)d_in[4];
    const float* Wih   = (const float*)d_in[5];
    const float* Whh   = (const float*)d_in[6];
    const float* bih   = (const float*)d_in[7];
    const float* bhh   = (const float*)d_in[8];
    const float* Wc    = (const float*)d_in[9];
    const float* bc    = (const float*)d_in[10];
    const float* Wout  = (const float*)d_in[11];
    const float* bout  = (const float*)d_in[12];

    float* out = (float*)d_out;
    long long need_h    = (long long)B * V + (long long)B * H;
    long long need_attn = need_h + (long long)B * L;
    float* out_h = ((long long)out_size >= need_h) ? out + (size_t)B * V : nullptr;
    int write_attn = ((long long)out_size >= need_attn) ? 1 : 0;

    float* pih; cudaGetSymbolAddress((void**)&pih, g_pih);
    float* phh; cudaGetSymbolAddress((void**)&phh, g_phh);
    float* pcc; cudaGetSymbolAddress((void**)&pcc, g_pcc);
    float* gx;  cudaGetSymbolAddress((void**)&gx,  g_x);
    float* gcat; cudaGetSymbolAddress((void**)&gcat, g_cat);
    float* gcatp; cudaGetSymbolAddress((void**)&gcatp, g_catp);

    // 1. gather x = emb[seq]
    gather_x_kernel<<<B, 256>>>(seq, emb);

    // 2. GRU GEMMs: gi = x@Wih^T, gh = h@Whh^T   (N=3072, K=1024, ksplit=4)
    gemm_kernel<<<dim3(3 * H / 128, 4, 2), 256>>>(
        gx, lh, Wih, Whh, pih, phh, nullptr, 3 * H, H, 4, 3 * H);

    // 3. gates -> h_new
    gru_gates_kernel<<<B * H / 256, 256>>>(lh, bih, bhh, out_h);

    // 4. flash attention over encoder_outputs (read once)
    attn1_kernel<<<(B * CHUNKS) / 4, 128>>>(enc);

    // 5. combine -> context, attn weights, prior copy
    combine_kernel<<<B, 256>>>(prior, out, write_attn);

    // 6. concat GEMM (N=1024, K=2048, ksplit=16) + reduce/tanh
    gemm_kernel<<<dim3(H / 128, 16, 1), 256>>>(
        gcat, gcat, Wc, Wc, pcc, pcc, nullptr, H, H2, 16, H);
    creduce_kernel<<<B * H / 256, 256>>>(bc);

    // 7. output GEMM (N=32000, K=1152, bias)
    gemm_kernel<<<dim3(V / 128, 1, 1), 256>>>(
        gcatp, gcatp, Wout, Wout, out, out, bout, V, KO, 1, V);
}

// round 6
// speedup vs baseline: 2.1152x; 1.4176x over previous
#include <cuda_runtime.h>
#include <cuda_bf16.h>
#include <math.h>
#include <stdint.h>

// Problem constants
#define B  64
#define L  2048
#define H  1024
#define V  32000
#define P  128
#define H2 2048          // 2*H
#define KO 1152          // H + P

#define CHUNKS 64        // L-splits for attention
#define LC (L / CHUNKS)  // 32
#define PS (H + 4)       // partial stride (16B aligned)

typedef unsigned long long U64;

union U64F2 { U64 u; float2 f; };

__device__ __forceinline__ U64 fma2(U64 a, U64 b, U64 c) {
    U64 d;
    asm("fma.rn.f32x2 %0, %1, %2, %3;" : "=l"(d) : "l"(a), "l"(b), "l"(c));
    return d;
}
__device__ __forceinline__ U64 mul2(U64 a, U64 b) {
    U64 d;
    asm("mul.rn.f32x2 %0, %1, %2;" : "=l"(d) : "l"(a), "l"(b));
    return d;
}
__device__ __forceinline__ float hsum2(U64 a) {
    U64F2 t; t.u = a; return t.f.x + t.f.y;
}
__device__ __forceinline__ U64 dup2(float x) {
    U64F2 t; t.f.x = x; t.f.y = x; return t.u;
}
__device__ __forceinline__ U64 pack2(float x, float y) {
    U64F2 t; t.f.x = x; t.f.y = y; return t.u;
}
__device__ __forceinline__ uint32_t f2tf32(float x) {
    uint32_t r;
    asm("cvt.rna.tf32.f32 %0, %1;" : "=r"(r) : "f"(x));
    return r;
}

// Scratch (device globals — no allocation allowed)
__device__ float g_x[B * H];                    // gathered embeddings
__device__ float g_hnew[B * H];
__device__ float g_cat[B * H2];                 // [h_new | context]
__device__ float g_catp[B * KO];                // [concat_out | prior]
__device__ float g_energy[B * L];
__device__ float g_part[B * CHUNKS * PS];       // ctx partial + (m, s)
__device__ float g_pih[4 * B * 3 * H];          // GRU ih partials (ksplit=4)
__device__ float g_phh[4 * B * 3 * H];          // GRU hh partials
__device__ float g_pcc[16 * B * H];             // concat partials (ksplit=16)

// ---------------------------------------------------------------------------
// Kernel 0: gather x = emb[seq]
// ---------------------------------------------------------------------------
__global__ void gather_x_kernel(const int* __restrict__ seq,
                                const float* __restrict__ emb)
{
    int b = blockIdx.x;
    int j = threadIdx.x;           // 256 threads, 4 floats each
    float4 v = *(const float4*)(emb + (size_t)seq[b] * H + j * 4);
    *(float4*)(g_x + (size_t)b * H + j * 4) = v;
}

// ---------------------------------------------------------------------------
// SIMT GEMM (used for GRU + concat): C[b,n] = sum_k A[b,k]*W[n,k]
// ---------------------------------------------------------------------------
#define GKT 32

__global__ void __launch_bounds__(256)
gemm_kernel(const float* __restrict__ A0, const float* __restrict__ A1,
            const float* __restrict__ W0, const float* __restrict__ W1,
            float* __restrict__ C0, float* __restrict__ C1,
            const float* __restrict__ bias,
            int N, int K, int ksplit, int ldc)
{
    __shared__ U64 As2[16][66];
    __shared__ U64 Ws2[16][130];

    const float* A = blockIdx.z ? A1 : A0;
    const float* W = blockIdx.z ? W1 : W0;
    float*       C = blockIdx.z ? C1 : C0;

    int vbase = blockIdx.x * 128;
    int kc    = K / ksplit;
    int k0    = blockIdx.y * kc;
    int tiles = kc / GKT;

    int tid = threadIdx.x;
    int vg  = tid >> 4;
    int bg  = tid & 15;
    int r8  = tid >> 3;
    int k4  = tid & 7;

    U64 acc[8][4];
    #pragma unroll
    for (int v = 0; v < 8; v++)
        #pragma unroll
        for (int j = 0; j < 4; j++) acc[v][j] = 0ull;

    float4 pa[2], pw[4];
    {
        int kt = k0 + k4 * 4;
        #pragma unroll
        for (int i = 0; i < 2; i++)
            pa[i] = *(const float4*)(A + (size_t)(r8 + i * 32) * K + kt);
        #pragma unroll
        for (int i = 0; i < 4; i++)
            pw[i] = *(const float4*)(W + (size_t)(vbase + r8 + i * 32) * K + kt);
    }

    for (int t = 0; t < tiles; t++) {
        __syncthreads();
        #pragma unroll
        for (int i = 0; i < 2; i++) {
            int b = r8 + i * 32;
            As2[2 * k4][b]     = pack2(pa[i].x, pa[i].y);
            As2[2 * k4 + 1][b] = pack2(pa[i].z, pa[i].w);
        }
        #pragma unroll
        for (int i = 0; i < 4; i++) {
            int n = r8 + i * 32;
            Ws2[2 * k4][n]     = pack2(pw[i].x, pw[i].y);
            Ws2[2 * k4 + 1][n] = pack2(pw[i].z, pw[i].w);
        }
        __syncthreads();

        if (t + 1 < tiles) {
            int kt = k0 + (t + 1) * GKT + k4 * 4;
            #pragma unroll
            for (int i = 0; i < 2; i++)
                pa[i] = *(const float4*)(A + (size_t)(r8 + i * 32) * K + kt);
            #pragma unroll
            for (int i = 0; i < 4; i++)
                pw[i] = *(const float4*)(W + (size_t)(vbase + r8 + i * 32) * K + kt);
        }

        #pragma unroll
        for (int kp = 0; kp < 16; kp++) {
            ulonglong2 a01 = *(const ulonglong2*)&As2[kp][bg * 4];
            ulonglong2 a23 = *(const ulonglong2*)&As2[kp][bg * 4 + 2];
            ulonglong2 w01 = *(const ulonglong2*)&Ws2[kp][vg * 8];
            ulonglong2 w23 = *(const ulonglong2*)&Ws2[kp][vg * 8 + 2];
            ulonglong2 w45 = *(const ulonglong2*)&Ws2[kp][vg * 8 + 4];
            ulonglong2 w67 = *(const ulonglong2*)&Ws2[kp][vg * 8 + 6];
            U64 a[4] = {a01.x, a01.y, a23.x, a23.y};
            U64 w[8] = {w01.x, w01.y, w23.x, w23.y, w45.x, w45.y, w67.x, w67.y};
            #pragma unroll
            for (int v = 0; v < 8; v++) {
                acc[v][0] = fma2(a[0], w[v], acc[v][0]);
                acc[v][1] = fma2(a[1], w[v], acc[v][1]);
                acc[v][2] = fma2(a[2], w[v], acc[v][2]);
                acc[v][3] = fma2(a[3], w[v], acc[v][3]);
            }
        }
    }

    float bv[8];
    #pragma unroll
    for (int v = 0; v < 8; v++)
        bv[v] = bias ? bias[vbase + vg * 8 + v] : 0.0f;

    float* Cb = bias ? C : (C + (size_t)blockIdx.y * 64 * ldc);
    #pragma unroll
    for (int j = 0; j < 4; j++) {
        int b = bg * 4 + j;
        float4 o0, o1;
        o0.x = hsum2(acc[0][j]) + bv[0];
        o0.y = hsum2(acc[1][j]) + bv[1];
        o0.z = hsum2(acc[2][j]) + bv[2];
        o0.w = hsum2(acc[3][j]) + bv[3];
        o1.x = hsum2(acc[4][j]) + bv[4];
        o1.y = hsum2(acc[5][j]) + bv[5];
        o1.z = hsum2(acc[6][j]) + bv[6];
        o1.w = hsum2(acc[7][j]) + bv[7];
        float* cp = Cb + (size_t)b * ldc + vbase + vg * 8;
        *(float4*)cp       = o0;
        *(float4*)(cp + 4) = o1;
    }
}

// ---------------------------------------------------------------------------
// GRU gates
// ---------------------------------------------------------------------------
__global__ void gru_gates_kernel(const float* __restrict__ lh,
                                 const float* __restrict__ bih,
                                 const float* __restrict__ bhh,
                                 float* __restrict__ out_h)
{
    int idx = blockIdx.x * 256 + threadIdx.x;
    int b = idx >> 10;
    int c = idx & 1023;

    float gir = 0.f, giz = 0.f, gin = 0.f, ghr = 0.f, ghz = 0.f, ghn = 0.f;
    #pragma unroll
    for (int s = 0; s < 4; s++) {
        size_t base = ((size_t)(s * 64 + b)) * (3 * H) + c;
        gir += g_pih[base];
        giz += g_pih[base + H];
        gin += g_pih[base + 2 * H];
        ghr += g_phh[base];
        ghz += g_phh[base + H];
        ghn += g_phh[base + 2 * H];
    }
    gir += bih[c]; giz += bih[c + H]; gin += bih[c + 2 * H];
    ghr += bhh[c]; ghz += bhh[c + H]; ghn += bhh[c + 2 * H];

    float r = 1.0f / (1.0f + expf(-(gir + ghr)));
    float z = 1.0f / (1.0f + expf(-(giz + ghz)));
    float n = tanhf(gin + r * ghn);
    float hp = lh[(size_t)b * H + c];
    float hn = (1.0f - z) * n + z * hp;

    g_hnew[(size_t)b * H + c] = hn;
    g_cat[(size_t)b * H2 + c] = hn;
    if (out_h) out_h[(size_t)b * H + c] = hn;
}

// ---------------------------------------------------------------------------
// concat reduce
// ---------------------------------------------------------------------------
__global__ void creduce_kernel(const float* __restrict__ bc)
{
    int idx = blockIdx.x * 256 + threadIdx.x;
    int b = idx >> 10;
    int c = idx & 1023;
    float s = 0.f;
    #pragma unroll
    for (int k = 0; k < 16; k++)
        s += g_pcc[((size_t)(k * 64 + b)) * H + c];
    g_catp[(size_t)b * KO + c] = tanhf(s + bc[c]);
}

// ---------------------------------------------------------------------------
// Attention pass 1 (flash-style, paired rows)
// ---------------------------------------------------------------------------
__global__ void __launch_bounds__(128)
attn1_kernel(const float* __restrict__ enc)
{
    int gw   = blockIdx.x * (blockDim.x >> 5) + (threadIdx.x >> 5);
    int lane = threadIdx.x & 31;
    int b    = gw >> 6;
    int ch   = gw & 63;
    int l0   = ch * LC;

    U64 q[16];
    const float* qp = g_hnew + (size_t)b * H;
    #pragma unroll
    for (int j = 0; j < 8; j++) {
        ulonglong2 v = *(const ulonglong2*)(qp + j * 128 + lane * 4);
        q[2 * j] = v.x; q[2 * j + 1] = v.y;
    }

    U64 cacc[16];
    #pragma unroll
    for (int i = 0; i < 16; i++) cacc[i] = 0ull;
    float m = -1e30f, s = 0.0f;

    #pragma unroll 1
    for (int li = 0; li < LC; li += 2) {
        const float* ep0 = enc + ((size_t)(l0 + li) * B + b) * H + lane * 4;
        const float* ep1 = ep0 + (size_t)B * H;

        U64 ev0[16], ev1[16];
        #pragma unroll
        for (int j = 0; j < 8; j++) {
            ulonglong2 v0 = *(const ulonglong2*)(ep0 + j * 128);
            ulonglong2 v1 = *(const ulonglong2*)(ep1 + j * 128);
            ev0[2 * j] = v0.x; ev0[2 * j + 1] = v0.y;
            ev1[2 * j] = v1.x; ev1[2 * j + 1] = v1.y;
        }

        U64 ea0 = 0ull, ea1 = 0ull;
        #pragma unroll
        for (int i = 0; i < 16; i++) {
            ea0 = fma2(ev0[i], q[i], ea0);
            ea1 = fma2(ev1[i], q[i], ea1);
        }
        float e0 = hsum2(ea0);
        float e1 = hsum2(ea1);
        #pragma unroll
        for (int off = 16; off > 0; off >>= 1) {
            e0 += __shfl_xor_sync(0xffffffffu, e0, off);
            e1 += __shfl_xor_sync(0xffffffffu, e1, off);
        }

        if (lane == 0) {
            g_energy[(size_t)b * L + l0 + li]     = e0;
            g_energy[(size_t)b * L + l0 + li + 1] = e1;
        }

        float mn = fmaxf(m, fmaxf(e0, e1));
        float sc = expf(m - mn);
        float p0 = expf(e0 - mn);
        float p1 = expf(e1 - mn);
        s = s * sc + p0 + p1;
        m = mn;
        U64 sc2 = dup2(sc), pp0 = dup2(p0), pp1 = dup2(p1);
        #pragma unroll
        for (int i = 0; i < 16; i++) {
            U64 t = mul2(cacc[i], sc2);
            t = fma2(ev0[i], pp0, t);
            cacc[i] = fma2(ev1[i], pp1, t);
        }
    }

    float* pb = g_part + (size_t)(b * CHUNKS + ch) * PS;
    #pragma unroll
    for (int j = 0; j < 8; j++) {
        ulonglong2 w;
        w.x = cacc[2 * j]; w.y = cacc[2 * j + 1];
        *(ulonglong2*)(pb + j * 128 + lane * 4) = w;
    }
    if (lane == 0) { pb[H] = m; pb[H + 1] = s; }
}

// ---------------------------------------------------------------------------
// Combine partials
// ---------------------------------------------------------------------------
__global__ void combine_kernel(const float* __restrict__ prior,
                               float* __restrict__ out, int write_attn)
{
    int b = blockIdx.x;
    int t = threadIdx.x;

    __shared__ float shm[CHUNKS], shs[CHUNKS], shw[CHUNKS];
    __shared__ float shM, shS;

    if (t < CHUNKS) {
        shm[t] = g_part[(size_t)(b * CHUNKS + t) * PS + H];
        shs[t] = g_part[(size_t)(b * CHUNKS + t) * PS + H + 1];
    }
    __syncthreads();
    if (t < 32) {
        float M = fmaxf(shm[t], shm[t + 32]);
        #pragma unroll
        for (int off = 16; off > 0; off >>= 1)
            M = fmaxf(M, __shfl_xor_sync(0xffffffffu, M, off));
        if (t == 0) shM = M;
    }
    __syncthreads();
    float M = shM;
    if (t < CHUNKS) shw[t] = expf(shm[t] - M);
    __syncthreads();
    if (t < 32) {
        float S = shs[t] * shw[t] + shs[t + 32] * shw[t + 32];
        #pragma unroll
        for (int off = 16; off > 0; off >>= 1)
            S += __shfl_xor_sync(0xffffffffu, S, off);
        if (t == 0) shS = S;
    }
    __syncthreads();
    float invS = 1.0f / shS;

    {
        int h = t * 4;
        float4 acc = make_float4(0.f, 0.f, 0.f, 0.f);
        #pragma unroll 4
        for (int i = 0; i < CHUNKS; i++) {
            float4 v = *(const float4*)(g_part + (size_t)(b * CHUNKS + i) * PS + h);
            float w = shw[i];
            acc.x += w * v.x; acc.y += w * v.y;
            acc.z += w * v.z; acc.w += w * v.w;
        }
        float4 o = make_float4(acc.x * invS, acc.y * invS, acc.z * invS, acc.w * invS);
        *(float4*)(g_cat + (size_t)b * H2 + H + h) = o;
    }

    if (write_attn) {
        size_t base = (size_t)B * V + (size_t)B * H + (size_t)b * L;
        for (int l = t; l < L; l += blockDim.x)
            out[base + l] = expf(g_energy[(size_t)b * L + l] - M) * invS;
    }

    for (int p = t; p < P; p += blockDim.x)
        g_catp[(size_t)b * KO + H + p] = prior[(size_t)b * P + p];
}

// ---------------------------------------------------------------------------
// Output GEMM via mma.sync tf32 (m16n8k8). Block = 128v x 64b, 8 warps (2x4),
// warp tile 64m x 16n. K-tiles of 32, register-prefetch single smem buffer.
// Smem stride 36 floats -> conflict-free fragment LDS.
// ---------------------------------------------------------------------------
#define OKT 32
#define OTILES (KO / OKT)   // 36
#define OSTRIDE 36

__device__ __forceinline__ void mma_tf32(float* d, uint32_t a0, uint32_t a1,
                                         uint32_t a2, uint32_t a3,
                                         uint32_t b0, uint32_t b1)
{
    asm volatile(
        "mma.sync.aligned.m16n8k8.row.col.f32.tf32.tf32.f32 "
        "{%0,%1,%2,%3}, {%4,%5,%6,%7}, {%8,%9}, {%0,%1,%2,%3};"
        : "+f"(d[0]), "+f"(d[1]), "+f"(d[2]), "+f"(d[3])
        : "r"(a0), "r"(a1), "r"(a2), "r"(a3), "r"(b0), "r"(b1));
}

__global__ void __launch_bounds__(256, 2)
out_gemm_tc_kernel(const float* __restrict__ Wout,
                   const float* __restrict__ bout,
                   float* __restrict__ outp)
{
    __shared__ uint32_t A_sm[128 * OSTRIDE];   // 18 KB (tf32 bits)
    __shared__ uint32_t B_sm[64 * OSTRIDE];    // 9 KB

    int tid   = threadIdx.x;
    int wid   = tid >> 5;
    int lane  = tid & 31;
    int gid   = lane >> 2;   // groupID 0..7
    int tig   = lane & 3;    // thread in group
    int vbase = blockIdx.x * 128;

    int warp_m = wid & 1;        // 0..1 -> m offset *64
    int warp_n = wid >> 1;       // 0..3 -> n offset *16
    int mbase  = warp_m * 64;
    int nbase  = warp_n * 16;

    float acc[4][2][4];
    #pragma unroll
    for (int mt = 0; mt < 4; mt++)
        #pragma unroll
        for (int nt = 0; nt < 2; nt++)
            #pragma unroll
            for (int i = 0; i < 4; i++) acc[mt][nt][i] = 0.0f;

    // prefetch registers: A 4 float4, B 2 float4 per thread
    float4 pa[4], pb[2];
    {
        #pragma unroll
        for (int j = 0; j < 4; j++) {
            int idx = tid + j * 256;             // 0..1023
            int row = idx >> 3, c4 = idx & 7;
            pa[j] = *(const float4*)(Wout + (size_t)(vbase + row) * KO + c4 * 4);
        }
        #pragma unroll
        for (int j = 0; j < 2; j++) {
            int idx = tid + j * 256;             // 0..511
            int row = idx >> 3, c4 = idx & 7;
            pb[j] = *(const float4*)(g_catp + (size_t)row * KO + c4 * 4);
        }
    }

    #pragma unroll 1
    for (int t = 0; t < OTILES; t++) {
        __syncthreads();
        #pragma unroll
        for (int j = 0; j < 4; j++) {
            int idx = tid + j * 256;
            int row = idx >> 3, c4 = idx & 7;
            uint32_t* p = &A_sm[row * OSTRIDE + c4 * 4];
            p[0] = f2tf32(pa[j].x); p[1] = f2tf32(pa[j].y);
            p[2] = f2tf32(pa[j].z); p[3] = f2tf32(pa[j].w);
        }
        #pragma unroll
        for (int j = 0; j < 2; j++) {
            int idx = tid + j * 256;
            int row = idx >> 3, c4 = idx & 7;
            uint32_t* p = &B_sm[row * OSTRIDE + c4 * 4];
            p[0] = f2tf32(pb[j].x); p[1] = f2tf32(pb[j].y);
            p[2] = f2tf32(pb[j].z); p[3] = f2tf32(pb[j].w);
        }
        __syncthreads();

        if (t + 1 < OTILES) {
            int kt = (t + 1) * OKT;
            #pragma unroll
            for (int j = 0; j < 4; j++) {
                int idx = tid + j * 256;
                int row = idx >> 3, c4 = idx & 7;
                pa[j] = *(const float4*)(Wout + (size_t)(vbase + row) * KO + kt + c4 * 4);
            }
            #pragma unroll
            for (int j = 0; j < 2; j++) {
                int idx = tid + j * 256;
                int row = idx >> 3, c4 = idx & 7;
                pb[j] = *(const float4*)(g_catp + (size_t)row * KO + kt + c4 * 4);
            }
        }

        #pragma unroll
        for (int kb = 0; kb < 4; kb++) {
            int kcol = kb * 8 + tig;

            uint32_t bfr[2][2];
            #pragma unroll
            for (int nt = 0; nt < 2; nt++) {
                int n0 = nbase + nt * 8 + gid;
                bfr[nt][0] = B_sm[n0 * OSTRIDE + kcol];
                bfr[nt][1] = B_sm[n0 * OSTRIDE + kcol + 4];
            }
            #pragma unroll
            for (int mt = 0; mt < 4; mt++) {
                int r0 = mbase + mt * 16 + gid;
                uint32_t a0 = A_sm[r0 * OSTRIDE + kcol];
                uint32_t a1 = A_sm[(r0 + 8) * OSTRIDE + kcol];
                uint32_t a2 = A_sm[r0 * OSTRIDE + kcol + 4];
                uint32_t a3 = A_sm[(r0 + 8) * OSTRIDE + kcol + 4];
                mma_tf32(acc[mt][0], a0, a1, a2, a3, bfr[0][0], bfr[0][1]);
                mma_tf32(acc[mt][1], a0, a1, a2, a3, bfr[1][0], bfr[1][1]);
            }
        }
    }

    // epilogue: D[v, b] -> outp[b*V + v] + bias[v]
    #pragma unroll
    for (int mt = 0; mt < 4; mt++) {
        int v0 = vbase + mbase + mt * 16 + gid;
        float bias0 = bout[v0];
        float bias1 = bout[v0 + 8];
        #pragma unroll
        for (int nt = 0; nt < 2; nt++) {
            int bcol = nbase + nt * 8 + 2 * tig;
            outp[(size_t)bcol * V + v0]           = acc[mt][nt][0] + bias0;
            outp[(size_t)(bcol + 1) * V + v0]     = acc[mt][nt][1] + bias0;
            outp[(size_t)bcol * V + v0 + 8]       = acc[mt][nt][2] + bias1;
            outp[(size_t)(bcol + 1) * V + v0 + 8] = acc[mt][nt][3] + bias1;
        }
    }
}

// ---------------------------------------------------------------------------
extern "C" void kernel_launch(void* const* d_in, const int* in_sizes, int n_in,
                              void* d_out, int out_size)
{
    const int*   seq   = (const int*)d_in[0];   // int32 (JAX x64 disabled)
    const float* lh    = (const float*)d_in[1];
    const float* enc   = (const float*)d_in[2];
    const float* prior = (const float*)d_in[3];
    const float* emb   = (const float*)d_in[4];
    const float* Wih   = (const float*)d_in[5];
    const float* Whh   = (const float*)d_in[6];
    const float* bih   = (const float*)d_in[7];
    const float* bhh   = (const float*)d_in[8];
    const float* Wc    = (const float*)d_in[9];
    const float* bc    = (const float*)d_in[10];
    const float* Wout  = (const float*)d_in[11];
    const float* bout  = (const float*)d_in[12];

    float* out = (float*)d_out;
    long long need_h    = (long long)B * V + (long long)B * H;
    long long need_attn = need_h + (long long)B * L;
    float* out_h = ((long long)out_size >= need_h) ? out + (size_t)B * V : nullptr;
    int write_attn = ((long long)out_size >= need_attn) ? 1 : 0;

    float* pih; cudaGetSymbolAddress((void**)&pih, g_pih);
    float* phh; cudaGetSymbolAddress((void**)&phh, g_phh);
    float* pcc; cudaGetSymbolAddress((void**)&pcc, g_pcc);
    float* gx;  cudaGetSymbolAddress((void**)&gx,  g_x);
    float* gcat; cudaGetSymbolAddress((void**)&gcat, g_cat);

    // 1. gather x = emb[seq]
    gather_x_kernel<<<B, 256>>>(seq, emb);

    // 2. GRU GEMMs: gi = x@Wih^T, gh = h@Whh^T   (N=3072, K=1024, ksplit=4)
    gemm_kernel<<<dim3(3 * H / 128, 4, 2), 256>>>(
        gx, lh, Wih, Whh, pih, phh, nullptr, 3 * H, H, 4, 3 * H);

    // 3. gates -> h_new
    gru_gates_kernel<<<B * H / 256, 256>>>(lh, bih, bhh, out_h);

    // 4. flash attention over encoder_outputs (read once)
    attn1_kernel<<<(B * CHUNKS) / 4, 128>>>(enc);

    // 5. combine -> context, attn weights, prior copy
    combine_kernel<<<B, 256>>>(prior, out, write_attn);

    // 6. concat GEMM (N=1024, K=2048, ksplit=16) + reduce/tanh
    gemm_kernel<<<dim3(H / 128, 16, 1), 256>>>(
        gcat, gcat, Wc, Wc, pcc, pcc, nullptr, H, H2, 16, H);
    creduce_kernel<<<B * H / 256, 256>>>(bc);

    // 7. output GEMM (N=32000, K=1152) via mma.sync tf32
    out_gemm_tc_kernel<<<V / 128, 256>>>(Wout, bout, out);
}